// round 4
// baseline (speedup 1.0000x reference)
#include <cuda_runtime.h>

// ---------------- problem constants ----------------
#define BB    2
#define CFEAT 128
#define HH    64
#define WW    128
#define GG    16
#define CPG   8
#define DDISP 48
#define HID   32
#define NEG   0.2f
#define EPSBN 1e-5f

#define SPA       (DDISP*HH*WW)       // 393216 per (b,channel)
#define VOL_ELEMS (BB*GG*SPA)
#define X_ELEMS   (BB*HID*SPA)

// ---------------- scratch ----------------
__device__ float  g_vol [VOL_ELEMS];
__device__ float  g_buf0[X_ELEMS];
__device__ float  g_buf1[X_ELEMS];
#define NSEG 48
__device__ float  g_part[HID*NSEG*2];
__device__ float2 g_ss  [HID];

// ---------------- packed f32x2 helpers (Blackwell FFMA2) ----------------
__device__ __forceinline__ unsigned long long ffma2(unsigned long long a,
                                                    unsigned long long b,
                                                    unsigned long long c)
{
    unsigned long long d;
    asm("fma.rn.f32x2 %0, %1, %2, %3;" : "=l"(d) : "l"(a), "l"(b), "l"(c));
    return d;
}
__device__ __forceinline__ unsigned long long packf2(float lo, float hi)
{
    unsigned long long d;
    asm("mov.b64 %0, {%1, %2};" : "=l"(d) : "f"(lo), "f"(hi));
    return d;
}
__device__ __forceinline__ float2 unpackf2(unsigned long long v)
{
    float lo, hi;
    asm("mov.b64 {%0, %1}, %2;" : "=f"(lo), "=f"(hi) : "l"(v));
    return make_float2(lo, hi);
}

// ---------------- volume build ----------------
__global__ void vol_kernel(const float* __restrict__ left,
                           const float* __restrict__ right,
                           float* __restrict__ vol)
{
    int h = blockIdx.x % HH;
    int g = (blockIdx.x / HH) % GG;
    int b = blockIdx.x / (HH*GG);
    int w = threadIdx.x;

    __shared__ float sR[CPG][WW];
    float l[CPG];
    const float* lp = left  + (((size_t)b*CFEAT + g*CPG)*HH + h)*WW + w;
    const float* rp = right + (((size_t)b*CFEAT + g*CPG)*HH + h)*WW + w;
#pragma unroll
    for (int c = 0; c < CPG; c++) {
        l[c]     = lp[(size_t)c*HH*WW];
        sR[c][w] = rp[(size_t)c*HH*WW];
    }
    __syncthreads();

    float* vp = vol + (((size_t)b*GG + g)*DDISP)*(HH*WW) + h*WW + w;
    for (int d = 0; d < DDISP; d++) {
        float s = 0.f;
        if (w >= d) {
            int ws = w - d;
#pragma unroll
            for (int c = 0; c < CPG; c++) s += l[c]*sR[c][ws];
        }
        vp[(size_t)d*HH*WW] = s * (1.0f/CPG);
    }
}

// ---------------- tiled direct conv3d (FFMA2 compute) ----------------
#define TD 2
#define TH 8
#define TW 16
#define CD 4
#define CH 10
#define CWD 18
#define CWP 19
#define CHUNK 4

template<int CIN, bool ACT>
__global__ __launch_bounds__(256)
void conv_kernel(const float* __restrict__ in,
                 const float* __restrict__ wg,   // [32][CIN][27]
                 float* __restrict__ out)
{
    __shared__ float  sIn[CHUNK][CD][CH][CWP];   // 12.2 KB
    __shared__ float2 sW2[CHUNK][HID][27];       // 27.6 KB (weights duplicated lane-wise)

    const int w0 = blockIdx.x * TW;
    const int h0 = blockIdx.y * TH;
    const int bz = blockIdx.z;
    const int b  = bz / (DDISP/TD);
    const int d0 = (bz % (DDISP/TD)) * TD;
    const int tid = threadIdx.x;

    const int coutg = tid >> 6;
    const int slot  = tid & 63;
    const int tdz   = slot >> 5;
    const int thy   = (slot >> 2) & 7;
    const int twx   = (slot & 3) * 4;
    const int cout0 = coutg * 8;

    unsigned long long acc[8][2];
    const unsigned long long z2 = packf2(0.f, 0.f);
#pragma unroll
    for (int o = 0; o < 8; o++) { acc[o][0] = z2; acc[o][1] = z2; }

    for (int c0 = 0; c0 < CIN; c0 += CHUNK) {
        __syncthreads();

        // stage weights duplicated into both f32x2 lanes
        for (int i = tid; i < CHUNK*HID*27; i += 256) {
            int c = i / (HID*27);
            int r = i % (HID*27);
            int o = r / 27;
            int k = r % 27;
            float wv = wg[((size_t)o*CIN + (c0 + c))*27 + k];
            sW2[c][o][k] = make_float2(wv, wv);
        }
        // stage input tile, fused BN affine + LeakyReLU
        for (int i = tid; i < CHUNK*CD*CH*CWD; i += 256) {
            int c  = i / (CD*CH*CWD);
            int r  = i % (CD*CH*CWD);
            int dz = r / (CH*CWD);
            int r2 = r % (CH*CWD);
            int hy = r2 / CWD;
            int wx = r2 % CWD;
            int gd = d0 - 1 + dz;
            int gh = h0 - 1 + hy;
            int gw = w0 - 1 + wx;
            float val = 0.f;
            if (gd >= 0 && gd < DDISP && gh >= 0 && gh < HH && gw >= 0 && gw < WW) {
                val = in[(((size_t)b*CIN + (c0 + c))*DDISP + gd)*(HH*WW) + gh*WW + gw];
                if (ACT) {
                    float2 s = g_ss[c0 + c];
                    val = fmaf(s.x, val, s.y);
                    val = (val > 0.f) ? val : NEG*val;
                }
            }
            sIn[c][dz][hy][wx] = val;
        }
        __syncthreads();

#pragma unroll 1
        for (int c = 0; c < CHUNK; c++) {
            const unsigned long long* wbase =
                (const unsigned long long*)&sW2[c][cout0][0];
#pragma unroll
            for (int kd = 0; kd < 3; kd++) {
#pragma unroll
                for (int kh = 0; kh < 3; kh++) {
                    float in6[6];
#pragma unroll
                    for (int v = 0; v < 6; v++)
                        in6[v] = sIn[c][tdz + kd][thy + kh][twx + v];
                    unsigned long long p[5];
#pragma unroll
                    for (int v = 0; v < 5; v++) p[v] = packf2(in6[v], in6[v+1]);
#pragma unroll
                    for (int kw = 0; kw < 3; kw++) {
                        const int kidx = (kd*3 + kh)*3 + kw;
                        const unsigned long long pa = p[kw];
                        const unsigned long long pb = p[kw + 2];
#pragma unroll
                        for (int o = 0; o < 8; o++) {
                            unsigned long long wv = wbase[o*27 + kidx];
                            acc[o][0] = ffma2(wv, pa, acc[o][0]);
                            acc[o][1] = ffma2(wv, pb, acc[o][1]);
                        }
                    }
                }
            }
        }
    }

    const int gd = d0 + tdz, gh = h0 + thy, gw = w0 + twx;
#pragma unroll
    for (int o = 0; o < 8; o++) {
        float2 a0 = unpackf2(acc[o][0]);
        float2 a1 = unpackf2(acc[o][1]);
        float4 r = make_float4(a0.x, a0.y, a1.x, a1.y);
        *(float4*)&out[(((size_t)b*HID + cout0 + o)*DDISP + gd)*(HH*WW) + gh*WW + gw] = r;
    }
}

// ---------------- BN stats (deterministic two-pass) ----------------
__global__ __launch_bounds__(256)
void stats_kernel(const float* __restrict__ x)
{
    const int ch  = blockIdx.y;
    const int seg = blockIdx.x;
    const int perch  = BB*SPA;
    const int perseg = perch / NSEG;
    const int base = seg * perseg;

    float s = 0.f, sq = 0.f;
    for (int i = base + threadIdx.x; i < base + perseg; i += 256) {
        int b = i / SPA;
        int r = i - b*SPA;
        float v = x[((size_t)b*HID + ch)*SPA + r];
        s  += v;
        sq += v*v;
    }
    __shared__ float rs[256], rq[256];
    rs[threadIdx.x] = s; rq[threadIdx.x] = sq;
    __syncthreads();
    for (int st = 128; st > 0; st >>= 1) {
        if (threadIdx.x < st) {
            rs[threadIdx.x] += rs[threadIdx.x + st];
            rq[threadIdx.x] += rq[threadIdx.x + st];
        }
        __syncthreads();
    }
    if (threadIdx.x == 0) {
        g_part[(ch*NSEG + seg)*2 + 0] = rs[0];
        g_part[(ch*NSEG + seg)*2 + 1] = rq[0];
    }
}

__global__ void finalize_kernel(const float* __restrict__ gamma,
                                const float* __restrict__ beta)
{
    int ch = threadIdx.x;
    if (ch >= HID) return;
    float s = 0.f, sq = 0.f;
    for (int k = 0; k < NSEG; k++) {
        s  += g_part[(ch*NSEG + k)*2 + 0];
        sq += g_part[(ch*NSEG + k)*2 + 1];
    }
    const float N = (float)(BB*SPA);
    float mean = s / N;
    float var  = fmaxf(sq / N - mean*mean, 0.f);
    float scale = gamma[ch] * rsqrtf(var + EPSBN);
    g_ss[ch] = make_float2(scale, beta[ch] - mean*scale);
}

// ---------------- final conv (32 -> 1), smem-tiled ----------------
__global__ __launch_bounds__(256)
void final_kernel(const float* __restrict__ x,
                  const float* __restrict__ wf,   // [1][32][27]
                  const float* __restrict__ bf,
                  float* __restrict__ out)
{
    __shared__ float sIn[CHUNK][CD][CH][CWP];
    __shared__ float sw[HID*27];
    __shared__ float2 sss[HID];

    const int w0 = blockIdx.x * TW;
    const int h0 = blockIdx.y * TH;
    const int bz = blockIdx.z;
    const int b  = bz / (DDISP/TD);
    const int d0 = (bz % (DDISP/TD)) * TD;
    const int tid = threadIdx.x;

    // one voxel per thread: 2(d) x 8(h) x 16(w) = 256
    const int tdz = tid >> 7;
    const int thy = (tid >> 4) & 7;
    const int twx = tid & 15;

    for (int i = tid; i < HID*27; i += 256) sw[i] = wf[i];
    if (tid < HID) sss[tid] = g_ss[tid];
    __syncthreads();     // weights/scales staged before first use

    float acc = 0.f;
    for (int c0 = 0; c0 < HID; c0 += CHUNK) {
        __syncthreads();
        for (int i = tid; i < CHUNK*CD*CH*CWD; i += 256) {
            int c  = i / (CD*CH*CWD);
            int r  = i % (CD*CH*CWD);
            int dz = r / (CH*CWD);
            int r2 = r % (CH*CWD);
            int hy = r2 / CWD;
            int wx = r2 % CWD;
            int gd = d0 - 1 + dz;
            int gh = h0 - 1 + hy;
            int gw = w0 - 1 + wx;
            float val = 0.f;
            if (gd >= 0 && gd < DDISP && gh >= 0 && gh < HH && gw >= 0 && gw < WW) {
                val = x[(((size_t)b*HID + (c0 + c))*DDISP + gd)*(HH*WW) + gh*WW + gw];
                float2 s = sss[c0 + c];
                val = fmaf(s.x, val, s.y);
                val = (val > 0.f) ? val : NEG*val;
            }
            sIn[c][dz][hy][wx] = val;
        }
        __syncthreads();

#pragma unroll 1
        for (int c = 0; c < CHUNK; c++) {
#pragma unroll
            for (int kd = 0; kd < 3; kd++) {
#pragma unroll
                for (int kh = 0; kh < 3; kh++) {
#pragma unroll
                    for (int kw = 0; kw < 3; kw++) {
                        acc = fmaf(sw[(c0 + c)*27 + (kd*3 + kh)*3 + kw],
                                   sIn[c][tdz + kd][thy + kh][twx + kw], acc);
                    }
                }
            }
        }
    }

    const int gd = d0 + tdz, gh = h0 + thy, gw = w0 + twx;
    out[(((size_t)b*DDISP + gd)*HH + gh)*WW + gw] = acc + bf[0];
}

// ---------------- launch ----------------
extern "C" void kernel_launch(void* const* d_in, const int* in_sizes, int n_in,
                              void* d_out, int out_size)
{
    const float* left  = (const float*)d_in[0];
    const float* right = (const float*)d_in[1];
    const float* w1 = (const float*)d_in[2];
    const float* g1 = (const float*)d_in[3];
    const float* b1 = (const float*)d_in[4];
    const float* w2 = (const float*)d_in[5];
    const float* g2 = (const float*)d_in[6];
    const float* b2 = (const float*)d_in[7];
    const float* w3 = (const float*)d_in[8];
    const float* g3 = (const float*)d_in[9];
    const float* b3 = (const float*)d_in[10];
    const float* w4 = (const float*)d_in[11];
    const float* g4 = (const float*)d_in[12];
    const float* b4 = (const float*)d_in[13];
    const float* wf = (const float*)d_in[14];
    const float* bf = (const float*)d_in[15];
    float* out = (float*)d_out;
    (void)in_sizes; (void)n_in; (void)out_size;

    float *vol, *buf0, *buf1;
    cudaGetSymbolAddress((void**)&vol,  g_vol);
    cudaGetSymbolAddress((void**)&buf0, g_buf0);
    cudaGetSymbolAddress((void**)&buf1, g_buf1);

    dim3 cgrid(WW/TW, HH/TH, BB*(DDISP/TD));
    dim3 sgrid(NSEG, HID);

    vol_kernel<<<BB*GG*HH, WW>>>(left, right, vol);

    conv_kernel<GG, false><<<cgrid, 256>>>(vol, w1, buf0);
    stats_kernel<<<sgrid, 256>>>(buf0);
    finalize_kernel<<<1, 32>>>(g1, b1);

    conv_kernel<HID, true><<<cgrid, 256>>>(buf0, w2, buf1);
    stats_kernel<<<sgrid, 256>>>(buf1);
    finalize_kernel<<<1, 32>>>(g2, b2);

    conv_kernel<HID, true><<<cgrid, 256>>>(buf1, w3, buf0);
    stats_kernel<<<sgrid, 256>>>(buf0);
    finalize_kernel<<<1, 32>>>(g3, b3);

    conv_kernel<HID, true><<<cgrid, 256>>>(buf0, w4, buf1);
    stats_kernel<<<sgrid, 256>>>(buf1);
    finalize_kernel<<<1, 32>>>(g4, b4);

    final_kernel<<<cgrid, 256>>>(buf1, wf, bf, out);
}

// round 5
// speedup vs baseline: 1.0016x; 1.0016x over previous
#include <cuda_runtime.h>

// ---------------- problem constants ----------------
#define BB    2
#define CFEAT 128
#define HH    64
#define WW    128
#define GG    16
#define CPG   8
#define DDISP 48
#define HID   32
#define NEG   0.2f
#define EPSBN 1e-5f

#define SPA       (DDISP*HH*WW)       // 393216 per (b,channel)
#define VOL_ELEMS (BB*GG*SPA)
#define X_ELEMS   (BB*HID*SPA)

// ---------------- scratch ----------------
__device__ float  g_vol [VOL_ELEMS];
__device__ float  g_buf0[X_ELEMS];
__device__ float  g_buf1[X_ELEMS];
#define NSEG 48
__device__ float  g_part[HID*NSEG*2];
__device__ float2 g_ss  [HID];

// ---------------- packed f32x2 helpers (Blackwell FFMA2) ----------------
__device__ __forceinline__ unsigned long long ffma2(unsigned long long a,
                                                    unsigned long long b,
                                                    unsigned long long c)
{
    unsigned long long d;
    asm("fma.rn.f32x2 %0, %1, %2, %3;" : "=l"(d) : "l"(a), "l"(b), "l"(c));
    return d;
}
__device__ __forceinline__ unsigned long long packf2(float lo, float hi)
{
    unsigned long long d;
    asm("mov.b64 %0, {%1, %2};" : "=l"(d) : "f"(lo), "f"(hi));
    return d;
}
__device__ __forceinline__ float2 unpackf2(unsigned long long v)
{
    float lo, hi;
    asm("mov.b64 {%0, %1}, %2;" : "=f"(lo), "=f"(hi) : "l"(v));
    return make_float2(lo, hi);
}

// ---------------- volume build ----------------
__global__ void vol_kernel(const float* __restrict__ left,
                           const float* __restrict__ right,
                           float* __restrict__ vol)
{
    int h = blockIdx.x % HH;
    int g = (blockIdx.x / HH) % GG;
    int b = blockIdx.x / (HH*GG);
    int w = threadIdx.x;

    __shared__ float sR[CPG][WW];
    float l[CPG];
    const float* lp = left  + (((size_t)b*CFEAT + g*CPG)*HH + h)*WW + w;
    const float* rp = right + (((size_t)b*CFEAT + g*CPG)*HH + h)*WW + w;
#pragma unroll
    for (int c = 0; c < CPG; c++) {
        l[c]     = lp[(size_t)c*HH*WW];
        sR[c][w] = rp[(size_t)c*HH*WW];
    }
    __syncthreads();

    float* vp = vol + (((size_t)b*GG + g)*DDISP)*(HH*WW) + h*WW + w;
    for (int d = 0; d < DDISP; d++) {
        float s = 0.f;
        if (w >= d) {
            int ws = w - d;
#pragma unroll
            for (int c = 0; c < CPG; c++) s += l[c]*sR[c][ws];
        }
        vp[(size_t)d*HH*WW] = s * (1.0f/CPG);
    }
}

// ---------------- tiled direct conv3d (FFMA2 compute) ----------------
#define TD 2
#define TH 8
#define TW 16
#define CD 4
#define CH 10
#define CWD 18
#define CWP 19
#define CHUNK 4

template<int CIN, bool ACT>
__global__ __launch_bounds__(256)
void conv_kernel(const float* __restrict__ in,
                 const float* __restrict__ wg,   // [32][CIN][27]
                 float* __restrict__ out)
{
    __shared__ float  sIn[CHUNK][CD][CH][CWP];   // 12.2 KB
    __shared__ float2 sW2[CHUNK][HID][27];       // 27.6 KB (weights duplicated lane-wise)

    const int w0 = blockIdx.x * TW;
    const int h0 = blockIdx.y * TH;
    const int bz = blockIdx.z;
    const int b  = bz / (DDISP/TD);
    const int d0 = (bz % (DDISP/TD)) * TD;
    const int tid = threadIdx.x;

    const int coutg = tid >> 6;
    const int slot  = tid & 63;
    const int tdz   = slot >> 5;
    const int thy   = (slot >> 2) & 7;
    const int twx   = (slot & 3) * 4;
    const int cout0 = coutg * 8;

    unsigned long long acc[8][2];
    const unsigned long long z2 = packf2(0.f, 0.f);
#pragma unroll
    for (int o = 0; o < 8; o++) { acc[o][0] = z2; acc[o][1] = z2; }

    for (int c0 = 0; c0 < CIN; c0 += CHUNK) {
        __syncthreads();

        // stage weights duplicated into both f32x2 lanes
        for (int i = tid; i < CHUNK*HID*27; i += 256) {
            int c = i / (HID*27);
            int r = i % (HID*27);
            int o = r / 27;
            int k = r % 27;
            float wv = wg[((size_t)o*CIN + (c0 + c))*27 + k];
            sW2[c][o][k] = make_float2(wv, wv);
        }
        // stage input tile, fused BN affine + LeakyReLU
        for (int i = tid; i < CHUNK*CD*CH*CWD; i += 256) {
            int c  = i / (CD*CH*CWD);
            int r  = i % (CD*CH*CWD);
            int dz = r / (CH*CWD);
            int r2 = r % (CH*CWD);
            int hy = r2 / CWD;
            int wx = r2 % CWD;
            int gd = d0 - 1 + dz;
            int gh = h0 - 1 + hy;
            int gw = w0 - 1 + wx;
            float val = 0.f;
            if (gd >= 0 && gd < DDISP && gh >= 0 && gh < HH && gw >= 0 && gw < WW) {
                val = in[(((size_t)b*CIN + (c0 + c))*DDISP + gd)*(HH*WW) + gh*WW + gw];
                if (ACT) {
                    float2 s = g_ss[c0 + c];
                    val = fmaf(s.x, val, s.y);
                    val = (val > 0.f) ? val : NEG*val;
                }
            }
            sIn[c][dz][hy][wx] = val;
        }
        __syncthreads();

#pragma unroll 1
        for (int c = 0; c < CHUNK; c++) {
            const unsigned long long* wbase =
                (const unsigned long long*)&sW2[c][cout0][0];
#pragma unroll
            for (int kd = 0; kd < 3; kd++) {
#pragma unroll
                for (int kh = 0; kh < 3; kh++) {
                    float in6[6];
#pragma unroll
                    for (int v = 0; v < 6; v++)
                        in6[v] = sIn[c][tdz + kd][thy + kh][twx + v];
                    unsigned long long p[5];
#pragma unroll
                    for (int v = 0; v < 5; v++) p[v] = packf2(in6[v], in6[v+1]);
#pragma unroll
                    for (int kw = 0; kw < 3; kw++) {
                        const int kidx = (kd*3 + kh)*3 + kw;
                        const unsigned long long pa = p[kw];
                        const unsigned long long pb = p[kw + 2];
#pragma unroll
                        for (int o = 0; o < 8; o++) {
                            unsigned long long wv = wbase[o*27 + kidx];
                            acc[o][0] = ffma2(wv, pa, acc[o][0]);
                            acc[o][1] = ffma2(wv, pb, acc[o][1]);
                        }
                    }
                }
            }
        }
    }

    const int gd = d0 + tdz, gh = h0 + thy, gw = w0 + twx;
#pragma unroll
    for (int o = 0; o < 8; o++) {
        float2 a0 = unpackf2(acc[o][0]);
        float2 a1 = unpackf2(acc[o][1]);
        float4 r = make_float4(a0.x, a0.y, a1.x, a1.y);
        *(float4*)&out[(((size_t)b*HID + cout0 + o)*DDISP + gd)*(HH*WW) + gh*WW + gw] = r;
    }
}

// ---------------- BN stats (deterministic two-pass) ----------------
__global__ __launch_bounds__(256)
void stats_kernel(const float* __restrict__ x)
{
    const int ch  = blockIdx.y;
    const int seg = blockIdx.x;
    const int perch  = BB*SPA;
    const int perseg = perch / NSEG;
    const int base = seg * perseg;

    float s = 0.f, sq = 0.f;
    for (int i = base + threadIdx.x; i < base + perseg; i += 256) {
        int b = i / SPA;
        int r = i - b*SPA;
        float v = x[((size_t)b*HID + ch)*SPA + r];
        s  += v;
        sq += v*v;
    }
    __shared__ float rs[256], rq[256];
    rs[threadIdx.x] = s; rq[threadIdx.x] = sq;
    __syncthreads();
    for (int st = 128; st > 0; st >>= 1) {
        if (threadIdx.x < st) {
            rs[threadIdx.x] += rs[threadIdx.x + st];
            rq[threadIdx.x] += rq[threadIdx.x + st];
        }
        __syncthreads();
    }
    if (threadIdx.x == 0) {
        g_part[(ch*NSEG + seg)*2 + 0] = rs[0];
        g_part[(ch*NSEG + seg)*2 + 1] = rq[0];
    }
}

__global__ void finalize_kernel(const float* __restrict__ gamma,
                                const float* __restrict__ beta)
{
    int ch = threadIdx.x;
    if (ch >= HID) return;
    float s = 0.f, sq = 0.f;
    for (int k = 0; k < NSEG; k++) {
        s  += g_part[(ch*NSEG + k)*2 + 0];
        sq += g_part[(ch*NSEG + k)*2 + 1];
    }
    const float N = (float)(BB*SPA);
    float mean = s / N;
    float var  = fmaxf(sq / N - mean*mean, 0.f);
    float scale = gamma[ch] * rsqrtf(var + EPSBN);
    g_ss[ch] = make_float2(scale, beta[ch] - mean*scale);
}

// ---------------- final conv (32 -> 1), smem-tiled ----------------
__global__ __launch_bounds__(256)
void final_kernel(const float* __restrict__ x,
                  const float* __restrict__ wf,   // [1][32][27]
                  const float* __restrict__ bf,
                  float* __restrict__ out)
{
    __shared__ float sIn[CHUNK][CD][CH][CWP];
    __shared__ float sw[HID*27];
    __shared__ float2 sss[HID];

    const int w0 = blockIdx.x * TW;
    const int h0 = blockIdx.y * TH;
    const int bz = blockIdx.z;
    const int b  = bz / (DDISP/TD);
    const int d0 = (bz % (DDISP/TD)) * TD;
    const int tid = threadIdx.x;

    // one voxel per thread: 2(d) x 8(h) x 16(w) = 256
    const int tdz = tid >> 7;
    const int thy = (tid >> 4) & 7;
    const int twx = tid & 15;

    for (int i = tid; i < HID*27; i += 256) sw[i] = wf[i];
    if (tid < HID) sss[tid] = g_ss[tid];
    __syncthreads();     // weights/scales staged before first use

    float acc = 0.f;
    for (int c0 = 0; c0 < HID; c0 += CHUNK) {
        __syncthreads();
        for (int i = tid; i < CHUNK*CD*CH*CWD; i += 256) {
            int c  = i / (CD*CH*CWD);
            int r  = i % (CD*CH*CWD);
            int dz = r / (CH*CWD);
            int r2 = r % (CH*CWD);
            int hy = r2 / CWD;
            int wx = r2 % CWD;
            int gd = d0 - 1 + dz;
            int gh = h0 - 1 + hy;
            int gw = w0 - 1 + wx;
            float val = 0.f;
            if (gd >= 0 && gd < DDISP && gh >= 0 && gh < HH && gw >= 0 && gw < WW) {
                val = x[(((size_t)b*HID + (c0 + c))*DDISP + gd)*(HH*WW) + gh*WW + gw];
                float2 s = sss[c0 + c];
                val = fmaf(s.x, val, s.y);
                val = (val > 0.f) ? val : NEG*val;
            }
            sIn[c][dz][hy][wx] = val;
        }
        __syncthreads();

#pragma unroll 1
        for (int c = 0; c < CHUNK; c++) {
#pragma unroll
            for (int kd = 0; kd < 3; kd++) {
#pragma unroll
                for (int kh = 0; kh < 3; kh++) {
#pragma unroll
                    for (int kw = 0; kw < 3; kw++) {
                        acc = fmaf(sw[(c0 + c)*27 + (kd*3 + kh)*3 + kw],
                                   sIn[c][tdz + kd][thy + kh][twx + kw], acc);
                    }
                }
            }
        }
    }

    const int gd = d0 + tdz, gh = h0 + thy, gw = w0 + twx;
    out[(((size_t)b*DDISP + gd)*HH + gh)*WW + gw] = acc + bf[0];
}

// ---------------- launch ----------------
extern "C" void kernel_launch(void* const* d_in, const int* in_sizes, int n_in,
                              void* d_out, int out_size)
{
    const float* left  = (const float*)d_in[0];
    const float* right = (const float*)d_in[1];
    const float* w1 = (const float*)d_in[2];
    const float* g1 = (const float*)d_in[3];
    const float* b1 = (const float*)d_in[4];
    const float* w2 = (const float*)d_in[5];
    const float* g2 = (const float*)d_in[6];
    const float* b2 = (const float*)d_in[7];
    const float* w3 = (const float*)d_in[8];
    const float* g3 = (const float*)d_in[9];
    const float* b3 = (const float*)d_in[10];
    const float* w4 = (const float*)d_in[11];
    const float* g4 = (const float*)d_in[12];
    const float* b4 = (const float*)d_in[13];
    const float* wf = (const float*)d_in[14];
    const float* bf = (const float*)d_in[15];
    float* out = (float*)d_out;
    (void)in_sizes; (void)n_in; (void)out_size;

    float *vol, *buf0, *buf1;
    cudaGetSymbolAddress((void**)&vol,  g_vol);
    cudaGetSymbolAddress((void**)&buf0, g_buf0);
    cudaGetSymbolAddress((void**)&buf1, g_buf1);

    dim3 cgrid(WW/TW, HH/TH, BB*(DDISP/TD));
    dim3 sgrid(NSEG, HID);

    vol_kernel<<<BB*GG*HH, WW>>>(left, right, vol);

    conv_kernel<GG, false><<<cgrid, 256>>>(vol, w1, buf0);
    stats_kernel<<<sgrid, 256>>>(buf0);
    finalize_kernel<<<1, 32>>>(g1, b1);

    conv_kernel<HID, true><<<cgrid, 256>>>(buf0, w2, buf1);
    stats_kernel<<<sgrid, 256>>>(buf1);
    finalize_kernel<<<1, 32>>>(g2, b2);

    conv_kernel<HID, true><<<cgrid, 256>>>(buf1, w3, buf0);
    stats_kernel<<<sgrid, 256>>>(buf0);
    finalize_kernel<<<1, 32>>>(g3, b3);

    conv_kernel<HID, true><<<cgrid, 256>>>(buf0, w4, buf1);
    stats_kernel<<<sgrid, 256>>>(buf1);
    finalize_kernel<<<1, 32>>>(g4, b4);

    final_kernel<<<cgrid, 256>>>(buf1, wf, bf, out);
}

// round 8
// speedup vs baseline: 2.1978x; 2.1944x over previous
#include <cuda_runtime.h>
#include <cuda_bf16.h>
#include <cstdint>

// ---------------- problem constants ----------------
#define BB    2
#define CFEAT 128
#define HH    64
#define WW    128
#define GG    16
#define CPG   8
#define DDISP 48
#define HID   32
#define NEG   0.2f
#define EPSBN 1e-5f

#define SPA       (DDISP*HH*WW)
#define VOL_ELEMS (BB*GG*SPA)
#define X_ELEMS   (BB*HID*SPA)

// ---------------- scratch ----------------
__device__ float   g_vol [VOL_ELEMS];
__device__ float   g_buf0[X_ELEMS];
__device__ float   g_buf1[X_ELEMS];
#define NSEG 48
__device__ float   g_part[HID*NSEG*2];
__device__ float2  g_ss  [HID];
// packed weight fragments: [tap 27][chunk NCH][half 2][j 8][n 32] u32 (bf16x2)
#define WP_LAYER_U32 (27*2*2*8*32)     // sized for NCH=2 (CIN=32); layer1 uses half
__device__ uint32_t g_wp[4*WP_LAYER_U32];

// ---------------- mma.sync m16n8k16 bf16 (base ISA, valid on sm_100) ----------------
__device__ __forceinline__ void mma16816(float d[4], const uint32_t a[4],
                                         uint32_t b0, uint32_t b1)
{
    asm volatile(
        "mma.sync.aligned.m16n8k16.row.col.f32.bf16.bf16.f32 "
        "{%0,%1,%2,%3}, {%4,%5,%6,%7}, {%8,%9}, {%0,%1,%2,%3};\n"
        : "+f"(d[0]), "+f"(d[1]), "+f"(d[2]), "+f"(d[3])
        : "r"(a[0]), "r"(a[1]), "r"(a[2]), "r"(a[3]), "r"(b0), "r"(b1));
}

__device__ __forceinline__ uint32_t pack_bf16x2(__nv_bfloat16 lo, __nv_bfloat16 hi)
{
    unsigned short u0 = *reinterpret_cast<unsigned short*>(&lo);
    unsigned short u1 = *reinterpret_cast<unsigned short*>(&hi);
    return (uint32_t)u0 | ((uint32_t)u1 << 16);
}

// ---------------- volume build ----------------
__global__ void vol_kernel(const float* __restrict__ left,
                           const float* __restrict__ right,
                           float* __restrict__ vol)
{
    int h = blockIdx.x % HH;
    int g = (blockIdx.x / HH) % GG;
    int b = blockIdx.x / (HH*GG);
    int w = threadIdx.x;

    __shared__ float sR[CPG][WW];
    float l[CPG];
    const float* lp = left  + (((size_t)b*CFEAT + g*CPG)*HH + h)*WW + w;
    const float* rp = right + (((size_t)b*CFEAT + g*CPG)*HH + h)*WW + w;
#pragma unroll
    for (int c = 0; c < CPG; c++) {
        l[c]     = lp[(size_t)c*HH*WW];
        sR[c][w] = rp[(size_t)c*HH*WW];
    }
    __syncthreads();

    float* vp = vol + (((size_t)b*GG + g)*DDISP)*(HH*WW) + h*WW + w;
    for (int d = 0; d < DDISP; d++) {
        float s = 0.f;
        if (w >= d) {
            int ws = w - d;
#pragma unroll
            for (int c = 0; c < CPG; c++) s += l[c]*sR[c][ws];
        }
        vp[(size_t)d*HH*WW] = s * (1.0f/CPG);
    }
}

// ---------------- weight fragment pre-pack ----------------
// dst[t][c][hf][j][n] = bf16x2( val(n, c*16+2j), val(n, c*16+2j+1) )
// hf=0: bf16(w) ; hf=1: bf16(w - float(bf16(w)))  (residual)
__global__ void wpack_kernel(const float* __restrict__ wg, int cin,
                             uint32_t* __restrict__ dst)
{
    const int t = blockIdx.x;            // 0..26
    const int nch = cin / 16;
    const int elems = nch * 512;         // 2 halves * 8 j * 32 n per chunk
    for (int i = threadIdx.x; i < elems; i += 256) {
        int n  = i & 31;
        int j  = (i >> 5) & 7;
        int hf = (i >> 8) & 1;
        int c  = i >> 9;
        int ci0 = c*16 + 2*j;
        float w0 = wg[((size_t)n*cin + ci0    )*27 + t];
        float w1 = wg[((size_t)n*cin + ci0 + 1)*27 + t];
        __nv_bfloat16 p0, p1;
        if (hf == 0) {
            p0 = __float2bfloat16_rn(w0);
            p1 = __float2bfloat16_rn(w1);
        } else {
            __nv_bfloat16 h0 = __float2bfloat16_rn(w0);
            __nv_bfloat16 h1 = __float2bfloat16_rn(w1);
            p0 = __float2bfloat16_rn(w0 - __bfloat162float(h0));
            p1 = __float2bfloat16_rn(w1 - __bfloat162float(h1));
        }
        dst[((((size_t)t*nch + c)*2 + hf)*8 + j)*32 + n] = pack_bf16x2(p0, p1);
    }
}

// ---------------- implicit-GEMM conv3d via mma.sync (bf16 split) ----------------
// CTA = one image row (b,d,h): 128 voxels x 32 couts. 8 warps x 16 voxels.
// K = ci (chunks of 16) x 27 taps, accumulated in fp32 fragments.
#define SA_STRIDE 136     // u32 stride per ci-pair row (conflict-free A loads)
#define SW_STRIDE 40      // u32 stride per j row (conflict-free B loads)
#define SD_STRIDE 132     // f32 stride per cout row (conflict-free D stage, f4-aligned)

template<int CIN, bool ACT>
__global__ __launch_bounds__(256)
void conv_mma(const float* __restrict__ in,
              const uint32_t* __restrict__ wp,
              float* __restrict__ out)
{
    constexpr int NCH = CIN / 16;
    constexpr int NPAIR = CIN / 2;
    constexpr int SW_U32 = 3*NCH*2*8*SW_STRIDE;      // staged B frags for 3 kw taps

    extern __shared__ __align__(16) uint8_t smem[];
    uint32_t* sW  = (uint32_t*)smem;                       // [3][NCH][2][8][40]
    uint32_t* sAh = sW + SW_U32;                           // [NPAIR][136]
    uint32_t* sAl = sAh + NPAIR*SA_STRIDE;
    float*    sD  = (float*)smem;                          // overlaps (used after compute)

    const int row = blockIdx.x;                  // 0..BB*DDISP*HH-1
    const int b = row / (DDISP*HH);
    const int d = (row / HH) % DDISP;
    const int h = row % HH;

    const int tid  = threadIdx.x;
    const int warp = tid >> 5;
    const int lane = tid & 31;
    const int g    = lane >> 2;      // group id (0..7)
    const int p4   = lane & 3;       // thread in group (0..3)
    const int m_base = warp * 16;

    float acc[4][4];
#pragma unroll
    for (int nb = 0; nb < 4; nb++)
#pragma unroll
        for (int v = 0; v < 4; v++) acc[nb][v] = 0.f;

#pragma unroll 1
    for (int kd = 0; kd < 3; kd++) {
        const int dd = d + kd - 1;
        if (dd < 0 || dd >= DDISP) continue;
#pragma unroll 1
        for (int kh = 0; kh < 3; kh++) {
            const int hh2 = h + kh - 1;
            if (hh2 < 0 || hh2 >= HH) continue;

            __syncthreads();   // previous compute done before restage

            // ---- stage activation row: ci-pairs packed, hi/lo split, fused BN+LReLU
            for (int e = tid; e < NPAIR*128; e += 256) {
                const int p = e >> 7;
                const int w = e & 127;
                const float* ip = in + (((size_t)b*CIN + 2*p)*DDISP + dd)*(HH*WW) + hh2*WW + w;
                float v0 = ip[0];
                float v1 = ip[(size_t)DDISP*HH*WW];
                if (ACT) {
                    float2 s0 = g_ss[2*p], s1 = g_ss[2*p+1];
                    v0 = fmaf(s0.x, v0, s0.y); v0 = (v0 > 0.f) ? v0 : NEG*v0;
                    v1 = fmaf(s1.x, v1, s1.y); v1 = (v1 > 0.f) ? v1 : NEG*v1;
                }
                __nv_bfloat16 h0 = __float2bfloat16_rn(v0);
                __nv_bfloat16 h1 = __float2bfloat16_rn(v1);
                __nv_bfloat16 l0 = __float2bfloat16_rn(v0 - __bfloat162float(h0));
                __nv_bfloat16 l1 = __float2bfloat16_rn(v1 - __bfloat162float(h1));
                sAh[p*SA_STRIDE + w + 1] = pack_bf16x2(h0, h1);
                sAl[p*SA_STRIDE + w + 1] = pack_bf16x2(l0, l1);
            }
            if (tid < CIN) {                 // zero pads at padded idx 0 and 129
                const int p  = tid >> 1;
                const int ix = (tid & 1) ? 129 : 0;
                sAh[p*SA_STRIDE + ix] = 0;
                sAl[p*SA_STRIDE + ix] = 0;
            }
            // ---- stage B fragments for the 3 kw taps of this (kd,kh)
            {
                const int t_base = (kd*3 + kh)*3;
                const uint32_t* src = wp + (size_t)t_base * (NCH*2*8*32);
                for (int i = tid; i < 3*NCH*2*8*32; i += 256) {
                    const int n  = i & 31;
                    const int j  = (i >> 5) & 7;
                    const int hf = (i >> 8) & 1;
                    const int cc = (i >> 9) % NCH;
                    const int kw = (i >> 9) / NCH;
                    sW[(((kw*NCH + cc)*2 + hf)*8 + j)*SW_STRIDE + n] = src[i];
                }
            }
            __syncthreads();

            // ---- compute: 3 kw taps x NCH chunks
#pragma unroll 1
            for (int kw = 0; kw < 3; kw++) {
#pragma unroll 1
                for (int c = 0; c < NCH; c++) {
                    const int bp  = c*8;
                    const int col = m_base + g + kw;   // padded w index for row m
                    uint32_t ah[4], al[4];
                    ah[0] = sAh[(bp + p4    )*SA_STRIDE + col];
                    ah[1] = sAh[(bp + p4    )*SA_STRIDE + col + 8];
                    ah[2] = sAh[(bp + p4 + 4)*SA_STRIDE + col];
                    ah[3] = sAh[(bp + p4 + 4)*SA_STRIDE + col + 8];
                    al[0] = sAl[(bp + p4    )*SA_STRIDE + col];
                    al[1] = sAl[(bp + p4    )*SA_STRIDE + col + 8];
                    al[2] = sAl[(bp + p4 + 4)*SA_STRIDE + col];
                    al[3] = sAl[(bp + p4 + 4)*SA_STRIDE + col + 8];

                    const uint32_t* wv = sW + ((kw*NCH + c)*2)*8*SW_STRIDE;
#pragma unroll
                    for (int nb = 0; nb < 4; nb++) {
                        const int nidx = nb*8 + g;
                        uint32_t bh0 = wv[(p4    )*SW_STRIDE + nidx];
                        uint32_t bh1 = wv[(p4 + 4)*SW_STRIDE + nidx];
                        uint32_t bl0 = wv[(8 + p4    )*SW_STRIDE + nidx];
                        uint32_t bl1 = wv[(8 + p4 + 4)*SW_STRIDE + nidx];
                        mma16816(acc[nb], ah, bh0, bh1);   // hi*hi
                        mma16816(acc[nb], ah, bl0, bl1);   // hi*lo
                        mma16816(acc[nb], al, bh0, bh1);   // lo*hi
                    }
                }
            }
        }
    }

    // ---- epilogue: smem transpose -> coalesced float4 stores
    __syncthreads();
#pragma unroll
    for (int nb = 0; nb < 4; nb++) {
        const int co = nb*8 + 2*p4;
        sD[(co    )*SD_STRIDE + m_base + g    ] = acc[nb][0];
        sD[(co + 1)*SD_STRIDE + m_base + g    ] = acc[nb][1];
        sD[(co    )*SD_STRIDE + m_base + g + 8] = acc[nb][2];
        sD[(co + 1)*SD_STRIDE + m_base + g + 8] = acc[nb][3];
    }
    __syncthreads();
    for (int i = tid; i < HID*32; i += 256) {
        const int co = i >> 5;
        const int q  = (i & 31) * 4;
        float4 v = *(const float4*)&sD[co*SD_STRIDE + q];
        *(float4*)&out[(((size_t)b*HID + co)*DDISP + d)*(HH*WW) + h*WW + q] = v;
    }
}

// ---------------- BN stats (deterministic two-pass) ----------------
__global__ __launch_bounds__(256)
void stats_kernel(const float* __restrict__ x)
{
    const int ch  = blockIdx.y;
    const int seg = blockIdx.x;
    const int perseg = (BB*SPA) / NSEG;
    const int base = seg * perseg;

    float s = 0.f, sq = 0.f;
    for (int i = base + threadIdx.x; i < base + perseg; i += 256) {
        int b = i / SPA;
        int r = i - b*SPA;
        float v = x[((size_t)b*HID + ch)*SPA + r];
        s  += v;
        sq += v*v;
    }
    __shared__ float rs[256], rq[256];
    rs[threadIdx.x] = s; rq[threadIdx.x] = sq;
    __syncthreads();
    for (int st = 128; st > 0; st >>= 1) {
        if (threadIdx.x < st) {
            rs[threadIdx.x] += rs[threadIdx.x + st];
            rq[threadIdx.x] += rq[threadIdx.x + st];
        }
        __syncthreads();
    }
    if (threadIdx.x == 0) {
        g_part[(ch*NSEG + seg)*2 + 0] = rs[0];
        g_part[(ch*NSEG + seg)*2 + 1] = rq[0];
    }
}

__global__ void finalize_kernel(const float* __restrict__ gamma,
                                const float* __restrict__ beta)
{
    int ch = threadIdx.x;
    if (ch >= HID) return;
    float s = 0.f, sq = 0.f;
    for (int k = 0; k < NSEG; k++) {
        s  += g_part[(ch*NSEG + k)*2 + 0];
        sq += g_part[(ch*NSEG + k)*2 + 1];
    }
    const float N = (float)(BB*SPA);
    float mean = s / N;
    float var  = fmaxf(sq / N - mean*mean, 0.f);
    float scale = gamma[ch] * rsqrtf(var + EPSBN);
    g_ss[ch] = make_float2(scale, beta[ch] - mean*scale);
}

// ---------------- final conv (32 -> 1), smem-tiled scalar ----------------
#define TD 2
#define TH 8
#define TW 16
#define CD 4
#define CH 10
#define CWD 18
#define CWP 19
#define CHUNK 4

__global__ __launch_bounds__(256)
void final_kernel(const float* __restrict__ x,
                  const float* __restrict__ wf,
                  const float* __restrict__ bf,
                  float* __restrict__ out)
{
    __shared__ float sIn[CHUNK][CD][CH][CWP];
    __shared__ float sw[HID*27];
    __shared__ float2 sss[HID];

    const int w0 = blockIdx.x * TW;
    const int h0 = blockIdx.y * TH;
    const int bz = blockIdx.z;
    const int b  = bz / (DDISP/TD);
    const int d0 = (bz % (DDISP/TD)) * TD;
    const int tid = threadIdx.x;

    const int tdz = tid >> 7;
    const int thy = (tid >> 4) & 7;
    const int twx = tid & 15;

    for (int i = tid; i < HID*27; i += 256) sw[i] = wf[i];
    if (tid < HID) sss[tid] = g_ss[tid];
    __syncthreads();

    float acc = 0.f;
    for (int c0 = 0; c0 < HID; c0 += CHUNK) {
        __syncthreads();
        for (int i = tid; i < CHUNK*CD*CH*CWD; i += 256) {
            int c  = i / (CD*CH*CWD);
            int r  = i % (CD*CH*CWD);
            int dz = r / (CH*CWD);
            int r2 = r % (CH*CWD);
            int hy = r2 / CWD;
            int wx = r2 % CWD;
            int gd = d0 - 1 + dz;
            int gh = h0 - 1 + hy;
            int gw = w0 - 1 + wx;
            float val = 0.f;
            if (gd >= 0 && gd < DDISP && gh >= 0 && gh < HH && gw >= 0 && gw < WW) {
                val = x[(((size_t)b*HID + (c0 + c))*DDISP + gd)*(HH*WW) + gh*WW + gw];
                float2 s = sss[c0 + c];
                val = fmaf(s.x, val, s.y);
                val = (val > 0.f) ? val : NEG*val;
            }
            sIn[c][dz][hy][wx] = val;
        }
        __syncthreads();

#pragma unroll 1
        for (int c = 0; c < CHUNK; c++) {
#pragma unroll
            for (int kd = 0; kd < 3; kd++) {
#pragma unroll
                for (int kh = 0; kh < 3; kh++) {
#pragma unroll
                    for (int kw = 0; kw < 3; kw++) {
                        acc = fmaf(sw[(c0 + c)*27 + (kd*3 + kh)*3 + kw],
                                   sIn[c][tdz + kd][thy + kh][twx + kw], acc);
                    }
                }
            }
        }
    }

    const int gd = d0 + tdz, gh = h0 + thy, gw = w0 + twx;
    out[(((size_t)b*DDISP + gd)*HH + gh)*WW + gw] = acc + bf[0];
}

// ---------------- launch ----------------
extern "C" void kernel_launch(void* const* d_in, const int* in_sizes, int n_in,
                              void* d_out, int out_size)
{
    const float* left  = (const float*)d_in[0];
    const float* right = (const float*)d_in[1];
    const float* w1 = (const float*)d_in[2];
    const float* g1 = (const float*)d_in[3];
    const float* b1 = (const float*)d_in[4];
    const float* w2 = (const float*)d_in[5];
    const float* g2 = (const float*)d_in[6];
    const float* b2 = (const float*)d_in[7];
    const float* w3 = (const float*)d_in[8];
    const float* g3 = (const float*)d_in[9];
    const float* b3 = (const float*)d_in[10];
    const float* w4 = (const float*)d_in[11];
    const float* g4 = (const float*)d_in[12];
    const float* b4 = (const float*)d_in[13];
    const float* wf = (const float*)d_in[14];
    const float* bf = (const float*)d_in[15];
    float* out = (float*)d_out;
    (void)in_sizes; (void)n_in; (void)out_size;

    float *vol, *buf0, *buf1;
    uint32_t* wp;
    cudaGetSymbolAddress((void**)&vol,  g_vol);
    cudaGetSymbolAddress((void**)&buf0, g_buf0);
    cudaGetSymbolAddress((void**)&buf1, g_buf1);
    cudaGetSymbolAddress((void**)&wp,   g_wp);

    // dynamic smem sizes (bytes)
    const int SD_BYTES = HID*SD_STRIDE*4;                              // 16896
    const int SM16_raw = (3*1*2*8*SW_STRIDE + 2*8*SA_STRIDE)*4;        // sW + 2*sA
    const int SM32_raw = (3*2*2*8*SW_STRIDE + 2*16*SA_STRIDE)*4;
    const int SMEM16 = (SM16_raw > SD_BYTES) ? SM16_raw : SD_BYTES;
    const int SMEM32 = (SM32_raw > SD_BYTES) ? SM32_raw : SD_BYTES;

    cudaFuncSetAttribute(conv_mma<16,false>, cudaFuncAttributeMaxDynamicSharedMemorySize, SMEM16);
    cudaFuncSetAttribute(conv_mma<32,true >, cudaFuncAttributeMaxDynamicSharedMemorySize, SMEM32);

    const int NROWS = BB*DDISP*HH;    // 6144
    dim3 cgrid(WW/TW, HH/TH, BB*(DDISP/TD));
    dim3 sgrid(NSEG, HID);

    // pack weight fragments (tiny)
    wpack_kernel<<<27, 256>>>(w1, 16, wp + 0*WP_LAYER_U32);
    wpack_kernel<<<27, 256>>>(w2, 32, wp + 1*WP_LAYER_U32);
    wpack_kernel<<<27, 256>>>(w3, 32, wp + 2*WP_LAYER_U32);
    wpack_kernel<<<27, 256>>>(w4, 32, wp + 3*WP_LAYER_U32);

    vol_kernel<<<BB*GG*HH, WW>>>(left, right, vol);

    conv_mma<16,false><<<NROWS, 256, SMEM16>>>(vol, wp + 0*WP_LAYER_U32, buf0);
    stats_kernel<<<sgrid, 256>>>(buf0);
    finalize_kernel<<<1, 32>>>(g1, b1);

    conv_mma<32,true><<<NROWS, 256, SMEM32>>>(buf0, wp + 1*WP_LAYER_U32, buf1);
    stats_kernel<<<sgrid, 256>>>(buf1);
    finalize_kernel<<<1, 32>>>(g2, b2);

    conv_mma<32,true><<<NROWS, 256, SMEM32>>>(buf1, wp + 2*WP_LAYER_U32, buf0);
    stats_kernel<<<sgrid, 256>>>(buf0);
    finalize_kernel<<<1, 32>>>(g3, b3);

    conv_mma<32,true><<<NROWS, 256, SMEM32>>>(buf0, wp + 3*WP_LAYER_U32, buf1);
    stats_kernel<<<sgrid, 256>>>(buf1);
    finalize_kernel<<<1, 32>>>(g4, b4);

    final_kernel<<<cgrid, 256>>>(buf1, wf, bf, out);
}

// round 9
// speedup vs baseline: 2.3661x; 1.0765x over previous
#include <cuda_runtime.h>
#include <cuda_bf16.h>
#include <cstdint>

// ---------------- problem constants ----------------
#define BB    2
#define CFEAT 128
#define HH    64
#define WW    128
#define GG    16
#define CPG   8
#define DDISP 48
#define HID   32
#define NEG   0.2f
#define EPSBN 1e-5f

#define SPA    (DDISP*HH*WW)
#define X_ELEMS (BB*HID*SPA)
#define NROWS  (BB*DDISP*HH)          // 6144
#define PKE    (BB*16*SPA)            // packed u32 elems (16 ci-pairs max)

// ---------------- scratch ----------------
__device__ float    g_buf0[X_ELEMS];          // fp32 conv output (reused per layer)
__device__ uint32_t g_ph[2*PKE];              // packed bf16-hi, ping/pong
__device__ uint32_t g_pl[2*PKE];              // packed bf16-lo, ping/pong
__device__ float    g_rsum[HID*NROWS];        // per-(ch,row) partial sums
__device__ float    g_rsq [HID*NROWS];
__device__ float2   g_ss  [HID];              // per-channel BN (scale, shift)
// packed weight fragments: [tap 27][chunk NCH][half 2][j 8][n 32] u32 (bf16x2)
#define WP_LAYER_U32 (27*2*2*8*32)
__device__ uint32_t g_wp[4*WP_LAYER_U32];

// ---------------- mma.sync m16n8k16 bf16 ----------------
__device__ __forceinline__ void mma16816(float d[4], const uint32_t a[4],
                                         uint32_t b0, uint32_t b1)
{
    asm volatile(
        "mma.sync.aligned.m16n8k16.row.col.f32.bf16.bf16.f32 "
        "{%0,%1,%2,%3}, {%4,%5,%6,%7}, {%8,%9}, {%0,%1,%2,%3};\n"
        : "+f"(d[0]), "+f"(d[1]), "+f"(d[2]), "+f"(d[3])
        : "r"(a[0]), "r"(a[1]), "r"(a[2]), "r"(a[3]), "r"(b0), "r"(b1));
}

__device__ __forceinline__ uint32_t pack_bf16x2(__nv_bfloat16 lo, __nv_bfloat16 hi)
{
    unsigned short u0 = *reinterpret_cast<unsigned short*>(&lo);
    unsigned short u1 = *reinterpret_cast<unsigned short*>(&hi);
    return (uint32_t)u0 | ((uint32_t)u1 << 16);
}

__device__ __forceinline__ void split_pack(float v0, float v1,
                                           uint32_t& hi, uint32_t& lo)
{
    __nv_bfloat16 h0 = __float2bfloat16_rn(v0);
    __nv_bfloat16 h1 = __float2bfloat16_rn(v1);
    __nv_bfloat16 l0 = __float2bfloat16_rn(v0 - __bfloat162float(h0));
    __nv_bfloat16 l1 = __float2bfloat16_rn(v1 - __bfloat162float(h1));
    hi = pack_bf16x2(h0, h1);
    lo = pack_bf16x2(l0, l1);
}

// ---------------- volume build, emitting packed hi/lo directly ----------------
// pair p packs vol channels (2p, 2p+1) = groups 2p,2p+1 (features p*16..p*16+15)
__global__ void vol_pack_kernel(const float* __restrict__ left,
                                const float* __restrict__ right,
                                uint32_t* __restrict__ ph,
                                uint32_t* __restrict__ pl)
{
    int h = blockIdx.x % HH;
    int p = (blockIdx.x / HH) % 8;
    int b = blockIdx.x / (HH*8);
    int w = threadIdx.x;                       // 128

    __shared__ float sR[16][WW];
    float l[16];
    const float* lp = left  + (((size_t)b*CFEAT + p*16)*HH + h)*WW + w;
    const float* rp = right + (((size_t)b*CFEAT + p*16)*HH + h)*WW + w;
#pragma unroll
    for (int c = 0; c < 16; c++) {
        l[c]     = lp[(size_t)c*HH*WW];
        sR[c][w] = rp[(size_t)c*HH*WW];
    }
    __syncthreads();

    uint32_t* hp = ph + ((size_t)(b*8 + p)*DDISP)*(HH*WW) + h*WW + w;
    uint32_t* lp2 = pl + ((size_t)(b*8 + p)*DDISP)*(HH*WW) + h*WW + w;
    for (int d = 0; d < DDISP; d++) {
        float s0 = 0.f, s1 = 0.f;
        if (w >= d) {
            int ws = w - d;
#pragma unroll
            for (int c = 0; c < 8; c++)  s0 += l[c]*sR[c][ws];
#pragma unroll
            for (int c = 8; c < 16; c++) s1 += l[c]*sR[c][ws];
        }
        s0 *= (1.0f/CPG); s1 *= (1.0f/CPG);
        uint32_t hi, lo;
        split_pack(s0, s1, hi, lo);
        hp [(size_t)d*HH*WW] = hi;
        lp2[(size_t)d*HH*WW] = lo;
    }
}

// ---------------- weight fragment pre-pack ----------------
__global__ void wpack_kernel(const float* __restrict__ wg, int cin,
                             uint32_t* __restrict__ dst)
{
    const int t = blockIdx.x;            // 0..26
    const int nch = cin / 16;
    const int elems = nch * 512;
    for (int i = threadIdx.x; i < elems; i += 256) {
        int n  = i & 31;
        int j  = (i >> 5) & 7;
        int hf = (i >> 8) & 1;
        int c  = i >> 9;
        int ci0 = c*16 + 2*j;
        float w0 = wg[((size_t)n*cin + ci0    )*27 + t];
        float w1 = wg[((size_t)n*cin + ci0 + 1)*27 + t];
        __nv_bfloat16 p0, p1;
        if (hf == 0) {
            p0 = __float2bfloat16_rn(w0);
            p1 = __float2bfloat16_rn(w1);
        } else {
            __nv_bfloat16 h0 = __float2bfloat16_rn(w0);
            __nv_bfloat16 h1 = __float2bfloat16_rn(w1);
            p0 = __float2bfloat16_rn(w0 - __bfloat162float(h0));
            p1 = __float2bfloat16_rn(w1 - __bfloat162float(h1));
        }
        dst[((((size_t)t*nch + c)*2 + hf)*8 + j)*32 + n] = pack_bf16x2(p0, p1);
    }
}

// ---------------- BN split pass: y(fp32) -> BN+LReLU -> packed hi/lo ----------------
__global__ __launch_bounds__(256)
void split_kernel(const float* __restrict__ y,
                  uint32_t* __restrict__ ph, uint32_t* __restrict__ pl)
{
    int idx = blockIdx.x * 256 + threadIdx.x;      // over BB*16*SPA
    int r = idx % SPA;
    int p = (idx / SPA) % 16;
    int b = idx / (16*SPA);

    float v0 = y[((size_t)b*HID + 2*p    )*SPA + r];
    float v1 = y[((size_t)b*HID + 2*p + 1)*SPA + r];
    float2 s0 = g_ss[2*p], s1 = g_ss[2*p + 1];
    v0 = fmaf(s0.x, v0, s0.y); v0 = (v0 > 0.f) ? v0 : NEG*v0;
    v1 = fmaf(s1.x, v1, s1.y); v1 = (v1 > 0.f) ? v1 : NEG*v1;
    uint32_t hi, lo;
    split_pack(v0, v1, hi, lo);
    ph[idx] = hi;
    pl[idx] = lo;
}

// ---------------- implicit-GEMM conv3d via mma.sync (bf16 split) ----------------
#define SA_STRIDE 136
#define SW_STRIDE 40
#define SD_STRIDE 132

template<int CIN>
__global__ __launch_bounds__(256)
void conv_mma(const uint32_t* __restrict__ ph,
              const uint32_t* __restrict__ pl,
              const uint32_t* __restrict__ wp,
              float* __restrict__ out)
{
    constexpr int NCH = CIN / 16;
    constexpr int NPAIR = CIN / 2;
    constexpr int SW_U32 = 3*NCH*2*8*SW_STRIDE;

    extern __shared__ __align__(16) uint8_t smem[];
    uint32_t* sW  = (uint32_t*)smem;                 // [3][NCH][2][8][40]
    uint32_t* sAh = sW + SW_U32;                     // [NPAIR][136]
    uint32_t* sAl = sAh + NPAIR*SA_STRIDE;
    float*    sD  = (float*)smem;                    // epilogue overlay
    float*    sSum = sD + HID*SD_STRIDE;             // [32][8]
    float*    sSq  = sSum + 256;

    const int row = blockIdx.x;                  // 0..NROWS-1
    const int b = row / (DDISP*HH);
    const int d = (row / HH) % DDISP;
    const int h = row % HH;

    const int tid  = threadIdx.x;
    const int warp = tid >> 5;
    const int lane = tid & 31;
    const int g    = lane >> 2;
    const int p4   = lane & 3;
    const int m_base = warp * 16;
    const int HW = HH*WW;

    float acc[4][4];
#pragma unroll
    for (int nb = 0; nb < 4; nb++)
#pragma unroll
        for (int v = 0; v < 4; v++) acc[nb][v] = 0.f;

    // zero the pad slots once (never overwritten by staging)
    if (tid < 2*NPAIR) {
        const int p  = tid >> 1;
        const int ix = (tid & 1) ? 129 : 0;
        sAh[p*SA_STRIDE + ix] = 0;
        sAl[p*SA_STRIDE + ix] = 0;
    }

#pragma unroll 1
    for (int kd = 0; kd < 3; kd++) {
        const int dd = d + kd - 1;
        if (dd < 0 || dd >= DDISP) continue;
#pragma unroll 1
        for (int kh = 0; kh < 3; kh++) {
            const int hh2 = h + kh - 1;
            if (hh2 < 0 || hh2 >= HH) continue;

            __syncthreads();   // previous compute done before restage

            // ---- stage activation row: pure u32 copies (uint4 loads)
            for (int i = tid; i < NPAIR*32; i += 256) {
                const int p  = i >> 5;
                const int w4 = (i & 31) * 4;
                const size_t src = ((size_t)(b*NPAIR + p)*DDISP + dd)*HW + hh2*WW + w4;
                uint4 vh = *(const uint4*)&ph[src];
                uint4 vl = *(const uint4*)&pl[src];
                uint32_t* da = &sAh[p*SA_STRIDE + w4 + 1];
                uint32_t* dl = &sAl[p*SA_STRIDE + w4 + 1];
                da[0] = vh.x; da[1] = vh.y; da[2] = vh.z; da[3] = vh.w;
                dl[0] = vl.x; dl[1] = vl.y; dl[2] = vl.z; dl[3] = vl.w;
            }
            // ---- stage B fragments for the 3 kw taps of this (kd,kh)
            {
                const int t_base = (kd*3 + kh)*3;
                const uint32_t* src = wp + (size_t)t_base * (NCH*2*8*32);
                for (int i = tid; i < 3*NCH*2*8*32; i += 256) {
                    const int n  = i & 31;
                    const int j  = (i >> 5) & 7;
                    const int hf = (i >> 8) & 1;
                    const int cc = (i >> 9) % NCH;
                    const int kw = (i >> 9) / NCH;
                    sW[(((kw*NCH + cc)*2 + hf)*8 + j)*SW_STRIDE + n] = src[i];
                }
            }
            __syncthreads();

            // ---- compute: 3 kw taps x NCH chunks
#pragma unroll 1
            for (int kw = 0; kw < 3; kw++) {
#pragma unroll 1
                for (int c = 0; c < NCH; c++) {
                    const int bp  = c*8;
                    const int col = m_base + g + kw;
                    uint32_t ah[4], al[4];
                    ah[0] = sAh[(bp + p4    )*SA_STRIDE + col];
                    ah[1] = sAh[(bp + p4    )*SA_STRIDE + col + 8];
                    ah[2] = sAh[(bp + p4 + 4)*SA_STRIDE + col];
                    ah[3] = sAh[(bp + p4 + 4)*SA_STRIDE + col + 8];
                    al[0] = sAl[(bp + p4    )*SA_STRIDE + col];
                    al[1] = sAl[(bp + p4    )*SA_STRIDE + col + 8];
                    al[2] = sAl[(bp + p4 + 4)*SA_STRIDE + col];
                    al[3] = sAl[(bp + p4 + 4)*SA_STRIDE + col + 8];

                    const uint32_t* wv = sW + ((kw*NCH + c)*2)*8*SW_STRIDE;
#pragma unroll
                    for (int nb = 0; nb < 4; nb++) {
                        const int nidx = nb*8 + g;
                        uint32_t bh0 = wv[(p4    )*SW_STRIDE + nidx];
                        uint32_t bh1 = wv[(p4 + 4)*SW_STRIDE + nidx];
                        uint32_t bl0 = wv[(8 + p4    )*SW_STRIDE + nidx];
                        uint32_t bl1 = wv[(8 + p4 + 4)*SW_STRIDE + nidx];
                        mma16816(acc[nb], ah, bh0, bh1);   // hi*hi
                        mma16816(acc[nb], ah, bl0, bl1);   // hi*lo
                        mma16816(acc[nb], al, bh0, bh1);   // lo*hi
                    }
                }
            }
        }
    }

    // ---- epilogue: smem transpose -> coalesced stores + fused BN partial sums
    __syncthreads();
#pragma unroll
    for (int nb = 0; nb < 4; nb++) {
        const int co = nb*8 + 2*p4;
        sD[(co    )*SD_STRIDE + m_base + g    ] = acc[nb][0];
        sD[(co + 1)*SD_STRIDE + m_base + g    ] = acc[nb][1];
        sD[(co    )*SD_STRIDE + m_base + g + 8] = acc[nb][2];
        sD[(co + 1)*SD_STRIDE + m_base + g + 8] = acc[nb][3];
    }
    __syncthreads();
    // write out
    for (int i = tid; i < HID*32; i += 256) {
        const int co = i >> 5;
        const int q  = (i & 31) * 4;
        float4 v = *(const float4*)&sD[co*SD_STRIDE + q];
        *(float4*)&out[(((size_t)b*HID + co)*DDISP + d)*(HH*WW) + h*WW + q] = v;
    }
    // per-(ch,row) partial sums (deterministic fixed order)
    {
        const int co = tid >> 3;
        const int sg = tid & 7;
        const float* rp = &sD[co*SD_STRIDE + sg*16];
        float s = 0.f, sq = 0.f;
#pragma unroll
        for (int j = 0; j < 16; j++) { float v = rp[j]; s += v; sq += v*v; }
        sSum[co*8 + sg] = s;
        sSq [co*8 + sg] = sq;
    }
    __syncthreads();
    if (tid < HID) {
        float S = 0.f, Q = 0.f;
#pragma unroll
        for (int k = 0; k < 8; k++) { S += sSum[tid*8 + k]; Q += sSq[tid*8 + k]; }
        g_rsum[(size_t)tid*NROWS + row] = S;
        g_rsq [(size_t)tid*NROWS + row] = Q;
    }
}

// ---------------- BN finalize: reduce per-row partials -> g_ss ----------------
__global__ __launch_bounds__(256)
void finalize2_kernel(const float* __restrict__ gamma,
                      const float* __restrict__ beta)
{
    const int ch = blockIdx.x;
    float s = 0.f, sq = 0.f;
    for (int r = threadIdx.x; r < NROWS; r += 256) {
        s  += g_rsum[(size_t)ch*NROWS + r];
        sq += g_rsq [(size_t)ch*NROWS + r];
    }
    __shared__ float rs[256], rq[256];
    rs[threadIdx.x] = s; rq[threadIdx.x] = sq;
    __syncthreads();
    for (int st = 128; st > 0; st >>= 1) {
        if (threadIdx.x < st) {
            rs[threadIdx.x] += rs[threadIdx.x + st];
            rq[threadIdx.x] += rq[threadIdx.x + st];
        }
        __syncthreads();
    }
    if (threadIdx.x == 0) {
        const float N = (float)(BB*SPA);
        float mean = rs[0] / N;
        float var  = fmaxf(rq[0] / N - mean*mean, 0.f);
        float scale = gamma[ch] * rsqrtf(var + EPSBN);
        g_ss[ch] = make_float2(scale, beta[ch] - mean*scale);
    }
}

// ---------------- final conv (32 -> 1), smem-tiled scalar ----------------
#define TD 2
#define TH 8
#define TW 16
#define CD 4
#define CH 10
#define CWD 18
#define CWP 19
#define CHUNK 4

__global__ __launch_bounds__(256)
void final_kernel(const float* __restrict__ x,
                  const float* __restrict__ wf,
                  const float* __restrict__ bf,
                  float* __restrict__ out)
{
    __shared__ float sIn[CHUNK][CD][CH][CWP];
    __shared__ float sw[HID*27];
    __shared__ float2 sss[HID];

    const int w0 = blockIdx.x * TW;
    const int h0 = blockIdx.y * TH;
    const int bz = blockIdx.z;
    const int b  = bz / (DDISP/TD);
    const int d0 = (bz % (DDISP/TD)) * TD;
    const int tid = threadIdx.x;

    const int tdz = tid >> 7;
    const int thy = (tid >> 4) & 7;
    const int twx = tid & 15;

    for (int i = tid; i < HID*27; i += 256) sw[i] = wf[i];
    if (tid < HID) sss[tid] = g_ss[tid];
    __syncthreads();

    float acc = 0.f;
    for (int c0 = 0; c0 < HID; c0 += CHUNK) {
        __syncthreads();
        for (int i = tid; i < CHUNK*CD*CH*CWD; i += 256) {
            int c  = i / (CD*CH*CWD);
            int r  = i % (CD*CH*CWD);
            int dz = r / (CH*CWD);
            int r2 = r % (CH*CWD);
            int hy = r2 / CWD;
            int wx = r2 % CWD;
            int gd = d0 - 1 + dz;
            int gh = h0 - 1 + hy;
            int gw = w0 - 1 + wx;
            float val = 0.f;
            if (gd >= 0 && gd < DDISP && gh >= 0 && gh < HH && gw >= 0 && gw < WW) {
                val = x[(((size_t)b*HID + (c0 + c))*DDISP + gd)*(HH*WW) + gh*WW + gw];
                float2 s = sss[c0 + c];
                val = fmaf(s.x, val, s.y);
                val = (val > 0.f) ? val : NEG*val;
            }
            sIn[c][dz][hy][wx] = val;
        }
        __syncthreads();

#pragma unroll 1
        for (int c = 0; c < CHUNK; c++) {
#pragma unroll
            for (int kd = 0; kd < 3; kd++) {
#pragma unroll
                for (int kh = 0; kh < 3; kh++) {
#pragma unroll
                    for (int kw = 0; kw < 3; kw++) {
                        acc = fmaf(sw[(c0 + c)*27 + (kd*3 + kh)*3 + kw],
                                   sIn[c][tdz + kd][thy + kh][twx + kw], acc);
                    }
                }
            }
        }
    }

    const int gd = d0 + tdz, gh = h0 + thy, gw = w0 + twx;
    out[(((size_t)b*DDISP + gd)*HH + gh)*WW + gw] = acc + bf[0];
}

// ---------------- launch ----------------
extern "C" void kernel_launch(void* const* d_in, const int* in_sizes, int n_in,
                              void* d_out, int out_size)
{
    const float* left  = (const float*)d_in[0];
    const float* right = (const float*)d_in[1];
    const float* w1 = (const float*)d_in[2];
    const float* g1 = (const float*)d_in[3];
    const float* b1 = (const float*)d_in[4];
    const float* w2 = (const float*)d_in[5];
    const float* g2 = (const float*)d_in[6];
    const float* b2 = (const float*)d_in[7];
    const float* w3 = (const float*)d_in[8];
    const float* g3 = (const float*)d_in[9];
    const float* b3 = (const float*)d_in[10];
    const float* w4 = (const float*)d_in[11];
    const float* g4 = (const float*)d_in[12];
    const float* b4 = (const float*)d_in[13];
    const float* wf = (const float*)d_in[14];
    const float* bf = (const float*)d_in[15];
    float* out = (float*)d_out;
    (void)in_sizes; (void)n_in; (void)out_size;

    float *buf;
    uint32_t *wp, *phb, *plb;
    cudaGetSymbolAddress((void**)&buf, g_buf0);
    cudaGetSymbolAddress((void**)&wp,  g_wp);
    cudaGetSymbolAddress((void**)&phb, g_ph);
    cudaGetSymbolAddress((void**)&plb, g_pl);
    uint32_t* ph0 = phb;        uint32_t* pl0 = plb;
    uint32_t* ph1 = phb + PKE;  uint32_t* pl1 = plb + PKE;

    // dynamic smem sizes (bytes)
    const int SD_BYTES = (HID*SD_STRIDE + 512)*4;
    const int SM16_raw = (3*1*2*8*SW_STRIDE + 2*8*SA_STRIDE)*4;
    const int SM32_raw = (3*2*2*8*SW_STRIDE + 2*16*SA_STRIDE)*4;
    const int SMEM16 = (SM16_raw > SD_BYTES) ? SM16_raw : SD_BYTES;
    const int SMEM32 = (SM32_raw > SD_BYTES) ? SM32_raw : SD_BYTES;

    cudaFuncSetAttribute(conv_mma<16>, cudaFuncAttributeMaxDynamicSharedMemorySize, SMEM16);
    cudaFuncSetAttribute(conv_mma<32>, cudaFuncAttributeMaxDynamicSharedMemorySize, SMEM32);

    dim3 cgrid(WW/TW, HH/TH, BB*(DDISP/TD));
    const int SPLIT_GRID = PKE/256;   // 49152

    // pack weight fragments (tiny)
    wpack_kernel<<<27, 256>>>(w1, 16, wp + 0*WP_LAYER_U32);
    wpack_kernel<<<27, 256>>>(w2, 32, wp + 1*WP_LAYER_U32);
    wpack_kernel<<<27, 256>>>(w3, 32, wp + 2*WP_LAYER_U32);
    wpack_kernel<<<27, 256>>>(w4, 32, wp + 3*WP_LAYER_U32);

    // volume directly in packed hi/lo form (ping buffer 0)
    vol_pack_kernel<<<BB*8*HH, 128>>>(left, right, ph0, pl0);

    conv_mma<16><<<NROWS, 256, SMEM16>>>(ph0, pl0, wp + 0*WP_LAYER_U32, buf);
    finalize2_kernel<<<HID, 256>>>(g1, b1);
    split_kernel<<<SPLIT_GRID, 256>>>(buf, ph1, pl1);

    conv_mma<32><<<NROWS, 256, SMEM32>>>(ph1, pl1, wp + 1*WP_LAYER_U32, buf);
    finalize2_kernel<<<HID, 256>>>(g2, b2);
    split_kernel<<<SPLIT_GRID, 256>>>(buf, ph0, pl0);

    conv_mma<32><<<NROWS, 256, SMEM32>>>(ph0, pl0, wp + 2*WP_LAYER_U32, buf);
    finalize2_kernel<<<HID, 256>>>(g3, b3);
    split_kernel<<<SPLIT_GRID, 256>>>(buf, ph1, pl1);

    conv_mma<32><<<NROWS, 256, SMEM32>>>(ph1, pl1, wp + 3*WP_LAYER_U32, buf);
    finalize2_kernel<<<HID, 256>>>(g4, b4);

    final_kernel<<<cgrid, 256>>>(buf, wf, bf, out);
}